// round 6
// baseline (speedup 1.0000x reference)
#include <cuda_runtime.h>
#include <cuda_bf16.h>

#define NN 50000
#define NE 800000
// channels fixed at 64, T fixed at 16

// ---------------- device scratch (static, no allocation) ----------------
__device__ float g_xa [NN * 64];     // mean(x, -1)
__device__ float g_h  [NN * 64];     // h @ W buffer
__device__ float g_agg[NN * 64];     // aggregated buffer
__device__ float g_deg [NN];
__device__ float g_dinv[NN];
__device__ int   g_cnt[NN];
__device__ int   g_off[NN + 1];
__device__ int   g_cur[NN];
__device__ int   g_csr_src[NE];
__device__ float g_csr_w [NE];

// ---------------- kernels ----------------

__global__ void zero_kernel() {
    int i = blockIdx.x * blockDim.x + threadIdx.x;
    if (i < NN) { g_deg[i] = 0.0f; g_cnt[i] = 0; }
}

// xa[n][c] = mean over T=16 of x[n][c][t]
__global__ void mean_kernel(const float* __restrict__ x) {
    int idx = blockIdx.x * blockDim.x + threadIdx.x;
    if (idx >= NN * 64) return;
    const float4* x4 = (const float4*)x;
    float4 v0 = x4[idx * 4 + 0];
    float4 v1 = x4[idx * 4 + 1];
    float4 v2 = x4[idx * 4 + 2];
    float4 v3 = x4[idx * 4 + 3];
    float s = (v0.x + v0.y + v0.z + v0.w) + (v1.x + v1.y + v1.z + v1.w)
            + (v2.x + v2.y + v2.z + v2.w) + (v3.x + v3.y + v3.z + v3.w);
    g_xa[idx] = s * 0.0625f;
}

// per-edge: weighted degree sum + dst histogram (2 edges per thread)
__global__ void edge_prep_kernel(const int* __restrict__ ei, const float* __restrict__ ea) {
    int t = blockIdx.x * blockDim.x + threadIdx.x;
    #pragma unroll
    for (int k = 0; k < 2; k++) {
        int e = t * 2 + k;
        if (e < NE) {
            int dst = ei[NE + e];
            float w = ea[e * 16 + 15];
            atomicAdd(&g_deg[dst], w);
            atomicAdd(&g_cnt[dst], 1);
        }
    }
}

// exclusive scan of g_cnt into g_off / g_cur (single block, 1024 threads),
// with g_dinv computed inline (independent per-node work folded in).
__global__ void scan_kernel() {
    __shared__ int wsum[32];
    __shared__ int carry;
    int tid = threadIdx.x, lane = tid & 31, wid = tid >> 5;
    if (tid == 0) carry = 0;
    __syncthreads();
    for (int base = 0; base < NN; base += 1024) {
        int i = base + tid;
        int v = 0;
        if (i < NN) {
            v = g_cnt[i];
            g_dinv[i] = rsqrtf(g_deg[i] + 1.0f);   // independent; no scan interaction
        }
        int incl = v;
        #pragma unroll
        for (int d = 1; d < 32; d <<= 1) {
            int t = __shfl_up_sync(0xffffffffu, incl, d);
            if (lane >= d) incl += t;
        }
        if (lane == 31) wsum[wid] = incl;
        __syncthreads();
        if (wid == 0) {
            int s = wsum[lane];
            #pragma unroll
            for (int d = 1; d < 32; d <<= 1) {
                int t = __shfl_up_sync(0xffffffffu, s, d);
                if (lane >= d) s += t;
            }
            wsum[lane] = s;
        }
        __syncthreads();
        int excl = carry + (wid ? wsum[wid - 1] : 0) + incl - v;
        if (i < NN) { g_off[i] = excl; g_cur[i] = excl; }
        int total = wsum[31];
        __syncthreads();
        if (tid == 0) carry += total;
        __syncthreads();
    }
    if (tid == 0) g_off[NN] = carry;
}

// scatter edges into CSR (by destination) with precomputed norm
__global__ void scatter_kernel(const int* __restrict__ ei, const float* __restrict__ ea) {
    int t = blockIdx.x * blockDim.x + threadIdx.x;
    #pragma unroll
    for (int k = 0; k < 2; k++) {
        int e = t * 2 + k;
        if (e < NE) {
            int src = ei[e];
            int dst = ei[NE + e];
            float w = ea[e * 16 + 15];
            float norm = g_dinv[src] * w * g_dinv[dst];
            int pos = atomicAdd(&g_cur[dst], 1);
            g_csr_src[pos] = src;
            g_csr_w[pos]   = norm;
        }
    }
}

// C[n][c] = sum_k A[n][k] * W[k][c] (+bias). 64x64 W in smem; 64 nodes/block,
// 256 threads, each thread: 4 nodes x 4 channels (float4).
__global__ void gemm64_kernel(const float* __restrict__ A, const float* __restrict__ W,
                              const float* __restrict__ bias, float* __restrict__ C) {
    __shared__ float4 Ws[64 * 16];      // [k][c4]
    __shared__ float  As[64][68];       // padded to avoid bank conflicts
    int tid = threadIdx.x;
    int node0 = blockIdx.x * 64;

    const float4* W4 = (const float4*)W;
    #pragma unroll
    for (int i = tid; i < 1024; i += 256) Ws[i] = W4[i];
    #pragma unroll
    for (int i = tid; i < 1024; i += 256) {
        int n = i >> 4, c4 = i & 15;
        int node = node0 + n;
        float4 v = (node < NN) ? ((const float4*)A)[node * 16 + c4]
                               : make_float4(0.f, 0.f, 0.f, 0.f);
        *((float4*)&As[n][c4 * 4]) = v;   // row base n*272B -> 16B aligned
    }
    __syncthreads();

    int ty = tid >> 4, c4 = tid & 15;
    float4 a0 = {0,0,0,0}, a1 = a0, a2 = a0, a3 = a0;
    #pragma unroll
    for (int k = 0; k < 64; k++) {
        float4 w = Ws[k * 16 + c4];
        float x0 = As[ty     ][k];
        float x1 = As[ty + 16][k];
        float x2 = As[ty + 32][k];
        float x3 = As[ty + 48][k];
        a0.x += x0 * w.x; a0.y += x0 * w.y; a0.z += x0 * w.z; a0.w += x0 * w.w;
        a1.x += x1 * w.x; a1.y += x1 * w.y; a1.z += x1 * w.z; a1.w += x1 * w.w;
        a2.x += x2 * w.x; a2.y += x2 * w.y; a2.z += x2 * w.z; a2.w += x2 * w.w;
        a3.x += x3 * w.x; a3.y += x3 * w.y; a3.z += x3 * w.z; a3.w += x3 * w.w;
    }
    if (bias) {
        float4 bb = ((const float4*)bias)[c4];
        a0.x += bb.x; a0.y += bb.y; a0.z += bb.z; a0.w += bb.w;
        a1.x += bb.x; a1.y += bb.y; a1.z += bb.z; a1.w += bb.w;
        a2.x += bb.x; a2.y += bb.y; a2.z += bb.z; a2.w += bb.w;
        a3.x += bb.x; a3.y += bb.y; a3.z += bb.z; a3.w += bb.w;
    }
    int n0 = node0 + ty, n1 = n0 + 16, n2 = n0 + 32, n3 = n0 + 48;
    float4* C4 = (float4*)C;
    if (n0 < NN) C4[n0 * 16 + c4] = a0;
    if (n1 < NN) C4[n1 * 16 + c4] = a1;
    if (n2 < NN) C4[n2 * 16 + c4] = a2;
    if (n3 < NN) C4[n3 * 16 + c4] = a3;
}

// pull aggregation: one warp per dst node, lane owns 2 channels (float2)
// out[n] = sum_{e in CSR(n)} w_e * h[src_e] + h[n]*dinv[n]^2 + bias; optional relu
// 4-wide software pipeline: four independent gathers in flight per iteration
// to cover ~250-cycle L2 hit latency (features are L2-resident, 12.8 MB).
__global__ void agg_kernel(const float* __restrict__ h, const float* __restrict__ bias,
                           float* __restrict__ out, int relu) {
    int gw = (blockIdx.x * blockDim.x + threadIdx.x) >> 5;
    if (gw >= NN) return;
    int lane = threadIdx.x & 31;
    int beg = g_off[gw], end = g_off[gw + 1];
    const float2* h2 = (const float2*)h;

    // self-term + bias loads issue early; overlap the gather loop
    float di = g_dinv[gw];
    float d2 = di * di;
    float2 self = __ldg(&h2[gw * 32 + lane]);
    float2 bb   = __ldg(&((const float2*)bias)[lane]);

    float ax = 0.f, ay = 0.f;
    int i = beg;
    // 4-wide: issue all four gathers before consuming any
    for (; i + 4 <= end; i += 4) {
        int   s0 = __ldg(&g_csr_src[i]);
        int   s1 = __ldg(&g_csr_src[i + 1]);
        int   s2 = __ldg(&g_csr_src[i + 2]);
        int   s3 = __ldg(&g_csr_src[i + 3]);
        float w0 = __ldg(&g_csr_w[i]);
        float w1 = __ldg(&g_csr_w[i + 1]);
        float w2 = __ldg(&g_csr_w[i + 2]);
        float w3 = __ldg(&g_csr_w[i + 3]);
        float2 v0 = __ldg(&h2[s0 * 32 + lane]);
        float2 v1 = __ldg(&h2[s1 * 32 + lane]);
        float2 v2 = __ldg(&h2[s2 * 32 + lane]);
        float2 v3 = __ldg(&h2[s3 * 32 + lane]);
        ax += w0 * v0.x + w1 * v1.x + w2 * v2.x + w3 * v3.x;
        ay += w0 * v0.y + w1 * v1.y + w2 * v2.y + w3 * v3.y;
    }
    for (; i < end; i++) {
        int   s = __ldg(&g_csr_src[i]);
        float w = __ldg(&g_csr_w[i]);
        float2 v = __ldg(&h2[s * 32 + lane]);
        ax += w * v.x;
        ay += w * v.y;
    }
    float ox = ax + self.x * d2 + bb.x;
    float oy = ay + self.y * d2 + bb.y;
    if (relu) { ox = fmaxf(ox, 0.f); oy = fmaxf(oy, 0.f); }
    ((float2*)out)[gw * 32 + lane] = make_float2(ox, oy);
}

// ---------------- launch ----------------
extern "C" void kernel_launch(void* const* d_in, const int* in_sizes, int n_in,
                              void* d_out, int out_size) {
    const float* x    = (const float*)d_in[0];
    const int*   ei   = (const int*)  d_in[1];
    const float* ea   = (const float*)d_in[2];
    const float* W1   = (const float*)d_in[3];
    const float* b1   = (const float*)d_in[4];
    const float* W2   = (const float*)d_in[5];
    const float* b2   = (const float*)d_in[6];
    const float* Wout = (const float*)d_in[7];
    const float* bout = (const float*)d_in[8];
    float* out = (float*)d_out;

    float *p_xa, *p_h, *p_agg;
    cudaGetSymbolAddress((void**)&p_xa,  g_xa);
    cudaGetSymbolAddress((void**)&p_h,   g_h);
    cudaGetSymbolAddress((void**)&p_agg, g_agg);

    const int TPB = 256;
    int nodeBlocks  = (NN + TPB - 1) / TPB;              // 196
    int edge2Blocks = (NE / 2 + TPB - 1) / TPB;          // 1563
    int meanBlocks  = (NN * 64 + 127) / 128;             // 25000
    int gemmBlocks  = (NN + 63) / 64;                    // 782
    int aggBlocks   = (NN * 32 + TPB - 1) / TPB;         // 6250

    zero_kernel<<<nodeBlocks, TPB>>>();
    mean_kernel<<<meanBlocks, 128>>>(x);
    edge_prep_kernel<<<edge2Blocks, TPB>>>(ei, ea);
    scan_kernel<<<1, 1024>>>();                          // also computes g_dinv
    scatter_kernel<<<edge2Blocks, TPB>>>(ei, ea);

    // layer 1: h = relu(agg(xa @ W1) + b1)
    gemm64_kernel<<<gemmBlocks, TPB>>>(p_xa, W1, nullptr, p_h);
    agg_kernel<<<aggBlocks, TPB>>>(p_h, b1, p_agg, 1);

    // layer 2: h = agg(h @ W2) + b2
    gemm64_kernel<<<gemmBlocks, TPB>>>(p_agg, W2, nullptr, p_h);
    agg_kernel<<<aggBlocks, TPB>>>(p_h, b2, p_agg, 0);

    // out = h @ Wout + bout
    gemm64_kernel<<<gemmBlocks, TPB>>>(p_agg, Wout, bout, out);
}

// round 12
// speedup vs baseline: 1.2786x; 1.2786x over previous
#include <cuda_runtime.h>
#include <cuda_bf16.h>

#define NN 50000
#define NE 800000
#define SCAN_CHUNK 512
#define NB ((NN + SCAN_CHUNK - 1) / SCAN_CHUNK)   // 98 chunks
// channels fixed at 64, T fixed at 16

// ---------------- device scratch (static, no allocation) ----------------
__device__ float g_xa [NN * 64];     // mean(x, -1)
__device__ float g_h  [NN * 64];     // h @ W buffer
__device__ float g_agg[NN * 64];     // aggregated buffer
__device__ float g_deg [NN];
__device__ float g_dinv[NN];
__device__ int   g_cnt[NN];
__device__ int   g_off[NN + 1];
__device__ int   g_cur[NN];
__device__ int   g_blocksum[NB];
__device__ int   g_blockoff[NB];
__device__ float g_ew [NE];          // densified edge weights (staged in edge_prep)
__device__ int   g_csr_src[NE];
__device__ float g_csr_w [NE];

// ---------------- kernels ----------------

__global__ void zero_kernel() {
    int i = blockIdx.x * blockDim.x + threadIdx.x;
    if (i < NN) { g_deg[i] = 0.0f; g_cnt[i] = 0; }
}

// xa[n][c] = mean over T=16 of x[n][c][t]
__global__ void mean_kernel(const float* __restrict__ x) {
    int idx = blockIdx.x * blockDim.x + threadIdx.x;
    if (idx >= NN * 64) return;
    const float4* x4 = (const float4*)x;
    float4 v0 = x4[idx * 4 + 0];
    float4 v1 = x4[idx * 4 + 1];
    float4 v2 = x4[idx * 4 + 2];
    float4 v3 = x4[idx * 4 + 3];
    float s = (v0.x + v0.y + v0.z + v0.w) + (v1.x + v1.y + v1.z + v1.w)
            + (v2.x + v2.y + v2.z + v2.w) + (v3.x + v3.y + v3.z + v3.w);
    g_xa[idx] = s * 0.0625f;
}

// per-edge: weighted degree sum + dst histogram (2 edges per thread)
// Also stages ea[:, -1] densely into g_ew so scatter avoids re-reading the
// strided edge_attr array (~51MB strided -> 3.2MB dense on the second pass).
__global__ void edge_prep_kernel(const int* __restrict__ ei, const float* __restrict__ ea) {
    int t = blockIdx.x * blockDim.x + threadIdx.x;
    #pragma unroll
    for (int k = 0; k < 2; k++) {
        int e = t * 2 + k;
        if (e < NE) {
            int dst = ei[NE + e];
            float w = ea[e * 16 + 15];
            g_ew[e] = w;
            atomicAdd(&g_deg[dst], w);
            atomicAdd(&g_cnt[dst], 1);
        }
    }
}

// ---- multi-block exclusive scan, phase 1: per-chunk local scan (full chip) ----
// 512 threads/block, chunk = 512 elements. Writes local-exclusive prefix into
// g_off, chunk total into g_blocksum. Also computes g_dinv (parallel).
__global__ void scan1_kernel() {
    __shared__ int wsum[16];
    int b = blockIdx.x, tid = threadIdx.x;
    int lane = tid & 31, wid = tid >> 5;
    int i = b * SCAN_CHUNK + tid;
    int v = 0;
    if (i < NN) {
        v = g_cnt[i];
        g_dinv[i] = rsqrtf(g_deg[i] + 1.0f);
    }
    int incl = v;
    #pragma unroll
    for (int d = 1; d < 32; d <<= 1) {
        int t = __shfl_up_sync(0xffffffffu, incl, d);
        if (lane >= d) incl += t;
    }
    if (lane == 31) wsum[wid] = incl;
    __syncthreads();
    if (wid == 0 && lane < 16) {
        int s = wsum[lane];
        #pragma unroll
        for (int d = 1; d < 16; d <<= 1) {
            int t = __shfl_up_sync(0x0000ffffu, s, d);
            if (lane >= d) s += t;
        }
        wsum[lane] = s;
    }
    __syncthreads();
    int excl = (wid ? wsum[wid - 1] : 0) + incl - v;
    if (i < NN) g_off[i] = excl;
    if (tid == 0) g_blocksum[b] = wsum[15];
}

// phase 2: scan the 98 chunk totals (one tiny block)
__global__ void scan2_kernel() {
    __shared__ int ws[4];
    int tid = threadIdx.x, lane = tid & 31, wid = tid >> 5;   // 128 threads
    int v = (tid < NB) ? g_blocksum[tid] : 0;
    int incl = v;
    #pragma unroll
    for (int d = 1; d < 32; d <<= 1) {
        int t = __shfl_up_sync(0xffffffffu, incl, d);
        if (lane >= d) incl += t;
    }
    if (lane == 31) ws[wid] = incl;
    __syncthreads();
    if (wid == 0 && lane < 4) {
        int s = ws[lane];
        #pragma unroll
        for (int d = 1; d < 4; d <<= 1) {
            int t = __shfl_up_sync(0x0000000fu, s, d);
            if (lane >= d) s += t;
        }
        ws[lane] = s;
    }
    __syncthreads();
    int excl = (wid ? ws[wid - 1] : 0) + incl - v;
    if (tid < NB) g_blockoff[tid] = excl;
    if (tid == 0) g_off[NN] = ws[3];
}

// phase 3: add chunk offsets, materialize g_cur
__global__ void scan3_kernel() {
    int i = blockIdx.x * blockDim.x + threadIdx.x;
    if (i < NN) {
        int o = g_off[i] + g_blockoff[i >> 9];   // 512-element chunks
        g_off[i] = o;
        g_cur[i] = o;
    }
}

// scatter edges into CSR (by destination) with precomputed norm.
// Reads staged dense weights (g_ew) instead of strided edge_attr.
__global__ void scatter_kernel(const int* __restrict__ ei) {
    int t = blockIdx.x * blockDim.x + threadIdx.x;
    #pragma unroll
    for (int k = 0; k < 2; k++) {
        int e = t * 2 + k;
        if (e < NE) {
            int src = ei[e];
            int dst = ei[NE + e];
            float w = g_ew[e];
            float norm = g_dinv[src] * w * g_dinv[dst];
            int pos = atomicAdd(&g_cur[dst], 1);
            g_csr_src[pos] = src;
            g_csr_w[pos]   = norm;
        }
    }
}

// C[n][c] = sum_k A[n][k] * W[k][c] (+bias). 64x64 W in smem; 64 nodes/block,
// 256 threads, each thread: 4 nodes x 4 channels (float4).
__global__ void gemm64_kernel(const float* __restrict__ A, const float* __restrict__ W,
                              const float* __restrict__ bias, float* __restrict__ C) {
    __shared__ float4 Ws[64 * 16];      // [k][c4]
    __shared__ float  As[64][68];       // padded to avoid bank conflicts
    int tid = threadIdx.x;
    int node0 = blockIdx.x * 64;

    const float4* W4 = (const float4*)W;
    #pragma unroll
    for (int i = tid; i < 1024; i += 256) Ws[i] = W4[i];
    #pragma unroll
    for (int i = tid; i < 1024; i += 256) {
        int n = i >> 4, c4 = i & 15;
        int node = node0 + n;
        float4 v = (node < NN) ? ((const float4*)A)[node * 16 + c4]
                               : make_float4(0.f, 0.f, 0.f, 0.f);
        *((float4*)&As[n][c4 * 4]) = v;   // row base n*272B -> 16B aligned
    }
    __syncthreads();

    int ty = tid >> 4, c4 = tid & 15;
    float4 a0 = {0,0,0,0}, a1 = a0, a2 = a0, a3 = a0;
    #pragma unroll
    for (int k = 0; k < 64; k++) {
        float4 w = Ws[k * 16 + c4];
        float x0 = As[ty     ][k];
        float x1 = As[ty + 16][k];
        float x2 = As[ty + 32][k];
        float x3 = As[ty + 48][k];
        a0.x += x0 * w.x; a0.y += x0 * w.y; a0.z += x0 * w.z; a0.w += x0 * w.w;
        a1.x += x1 * w.x; a1.y += x1 * w.y; a1.z += x1 * w.z; a1.w += x1 * w.w;
        a2.x += x2 * w.x; a2.y += x2 * w.y; a2.z += x2 * w.z; a2.w += x2 * w.w;
        a3.x += x3 * w.x; a3.y += x3 * w.y; a3.z += x3 * w.z; a3.w += x3 * w.w;
    }
    if (bias) {
        float4 bb = ((const float4*)bias)[c4];
        a0.x += bb.x; a0.y += bb.y; a0.z += bb.z; a0.w += bb.w;
        a1.x += bb.x; a1.y += bb.y; a1.z += bb.z; a1.w += bb.w;
        a2.x += bb.x; a2.y += bb.y; a2.z += bb.z; a2.w += bb.w;
        a3.x += bb.x; a3.y += bb.y; a3.z += bb.z; a3.w += bb.w;
    }
    int n0 = node0 + ty, n1 = n0 + 16, n2 = n0 + 32, n3 = n0 + 48;
    float4* C4 = (float4*)C;
    if (n0 < NN) C4[n0 * 16 + c4] = a0;
    if (n1 < NN) C4[n1 * 16 + c4] = a1;
    if (n2 < NN) C4[n2 * 16 + c4] = a2;
    if (n3 < NN) C4[n3 * 16 + c4] = a3;
}

// pull aggregation: one warp per dst node, lane owns 2 channels (float2)
// out[n] = sum_{e in CSR(n)} w_e * h[src_e] + h[n]*dinv[n]^2 + bias; optional relu
// 4-wide software pipeline: four independent gathers in flight per iteration
// to cover ~250-cycle L2 hit latency (features are L2-resident, 12.8 MB).
__global__ void agg_kernel(const float* __restrict__ h, const float* __restrict__ bias,
                           float* __restrict__ out, int relu) {
    int gw = (blockIdx.x * blockDim.x + threadIdx.x) >> 5;
    if (gw >= NN) return;
    int lane = threadIdx.x & 31;
    int beg = g_off[gw], end = g_off[gw + 1];
    const float2* h2 = (const float2*)h;

    // self-term + bias loads issue early; overlap the gather loop
    float di = g_dinv[gw];
    float d2 = di * di;
    float2 self = __ldg(&h2[gw * 32 + lane]);
    float2 bb   = __ldg(&((const float2*)bias)[lane]);

    float ax = 0.f, ay = 0.f;
    int i = beg;
    // 4-wide: issue all four gathers before consuming any
    for (; i + 4 <= end; i += 4) {
        int   s0 = __ldg(&g_csr_src[i]);
        int   s1 = __ldg(&g_csr_src[i + 1]);
        int   s2 = __ldg(&g_csr_src[i + 2]);
        int   s3 = __ldg(&g_csr_src[i + 3]);
        float w0 = __ldg(&g_csr_w[i]);
        float w1 = __ldg(&g_csr_w[i + 1]);
        float w2 = __ldg(&g_csr_w[i + 2]);
        float w3 = __ldg(&g_csr_w[i + 3]);
        float2 v0 = __ldg(&h2[s0 * 32 + lane]);
        float2 v1 = __ldg(&h2[s1 * 32 + lane]);
        float2 v2 = __ldg(&h2[s2 * 32 + lane]);
        float2 v3 = __ldg(&h2[s3 * 32 + lane]);
        ax += w0 * v0.x + w1 * v1.x + w2 * v2.x + w3 * v3.x;
        ay += w0 * v0.y + w1 * v1.y + w2 * v2.y + w3 * v3.y;
    }
    for (; i < end; i++) {
        int   s = __ldg(&g_csr_src[i]);
        float w = __ldg(&g_csr_w[i]);
        float2 v = __ldg(&h2[s * 32 + lane]);
        ax += w * v.x;
        ay += w * v.y;
    }
    float ox = ax + self.x * d2 + bb.x;
    float oy = ay + self.y * d2 + bb.y;
    if (relu) { ox = fmaxf(ox, 0.f); oy = fmaxf(oy, 0.f); }
    ((float2*)out)[gw * 32 + lane] = make_float2(ox, oy);
}

// ---------------- launch ----------------
extern "C" void kernel_launch(void* const* d_in, const int* in_sizes, int n_in,
                              void* d_out, int out_size) {
    const float* x    = (const float*)d_in[0];
    const int*   ei   = (const int*)  d_in[1];
    const float* ea   = (const float*)d_in[2];
    const float* W1   = (const float*)d_in[3];
    const float* b1   = (const float*)d_in[4];
    const float* W2   = (const float*)d_in[5];
    const float* b2   = (const float*)d_in[6];
    const float* Wout = (const float*)d_in[7];
    const float* bout = (const float*)d_in[8];
    float* out = (float*)d_out;

    float *p_xa, *p_h, *p_agg;
    cudaGetSymbolAddress((void**)&p_xa,  g_xa);
    cudaGetSymbolAddress((void**)&p_h,   g_h);
    cudaGetSymbolAddress((void**)&p_agg, g_agg);

    const int TPB = 256;
    int nodeBlocks  = (NN + TPB - 1) / TPB;              // 196
    int edge2Blocks = (NE / 2 + TPB - 1) / TPB;          // 1563
    int meanBlocks  = (NN * 64 + 127) / 128;             // 25000
    int gemmBlocks  = (NN + 63) / 64;                    // 782
    int aggBlocks   = (NN * 32 + TPB - 1) / TPB;         // 6250

    zero_kernel<<<nodeBlocks, TPB>>>();
    mean_kernel<<<meanBlocks, 128>>>(x);
    edge_prep_kernel<<<edge2Blocks, TPB>>>(ei, ea);
    scan1_kernel<<<NB, SCAN_CHUNK>>>();                  // also computes g_dinv
    scan2_kernel<<<1, 128>>>();
    scan3_kernel<<<nodeBlocks, TPB>>>();
    scatter_kernel<<<edge2Blocks, TPB>>>(ei);

    // layer 1: h = relu(agg(xa @ W1) + b1)
    gemm64_kernel<<<gemmBlocks, TPB>>>(p_xa, W1, nullptr, p_h);
    agg_kernel<<<aggBlocks, TPB>>>(p_h, b1, p_agg, 1);

    // layer 2: h = agg(h @ W2) + b2
    gemm64_kernel<<<gemmBlocks, TPB>>>(p_agg, W2, nullptr, p_h);
    agg_kernel<<<aggBlocks, TPB>>>(p_h, b2, p_agg, 0);

    // out = h @ Wout + bout
    gemm64_kernel<<<gemmBlocks, TPB>>>(p_agg, Wout, bout, out);
}